// round 5
// baseline (speedup 1.0000x reference)
#include <cuda_runtime.h>
#include <cstdint>

// EConv via per-launch CSR build:
//   out[n,:] = sum_{e: dst[e]==n} x[src[e],:] * edge_attr[e,:]
// d_in[0]: x          float32 [100000*64]
// d_in[1]: edge_index int32   [2*1000000]  (row 0 = dst, row 1 = src)
// d_in[2]: edge_attr  float32 [1000000*64]
// d_out:   float32 [100000*64]
//
// Pipeline (all in one graph, no allocs — __device__ scratch):
//  k_zero_off -> k_hist -> k_scan1 -> k_scan2 -> k_scan3 -> k_scatter -> k_econv

#define N_NODES 100000
#define E_MAX   1000000
#define D4      16          // 16 float4 chunks per 64-float row
#define SCAN_B  1024
#define SCAN_NB ((N_NODES + 1 + SCAN_B - 1) / SCAN_B)   // 98

__device__ int g_off[N_NODES + 1];   // counts -> inclusive-scanned offsets
__device__ int g_cur[N_NODES];       // scatter cursors (= row starts)
__device__ int g_eid[E_MAX];         // edge ids grouped by dst
__device__ int g_part[SCAN_NB + 32]; // per-block scan partials

__global__ void k_zero_off() {
    int i = blockIdx.x * blockDim.x + threadIdx.x;
    if (i <= N_NODES) g_off[i] = 0;
}

__global__ void k_hist(const int* __restrict__ dst, int E) {
    int e = blockIdx.x * blockDim.x + threadIdx.x;
    if (e < E) atomicAdd(&g_off[__ldcs(&dst[e]) + 1], 1);
}

// Inclusive scan of g_off in 1024-wide blocks; block totals to g_part.
__global__ __launch_bounds__(SCAN_B) void k_scan1() {
    __shared__ int warp_sums[32];
    int i = blockIdx.x * SCAN_B + threadIdx.x;
    int lane = threadIdx.x & 31, wid = threadIdx.x >> 5;
    int s = (i <= N_NODES) ? g_off[i] : 0;
#pragma unroll
    for (int d = 1; d < 32; d <<= 1) {
        int t = __shfl_up_sync(~0u, s, d);
        if (lane >= d) s += t;
    }
    if (lane == 31) warp_sums[wid] = s;
    __syncthreads();
    if (wid == 0) {
        int ws = warp_sums[lane];
#pragma unroll
        for (int d = 1; d < 32; d <<= 1) {
            int t = __shfl_up_sync(~0u, ws, d);
            if (lane >= d) ws += t;
        }
        warp_sums[lane] = ws;
    }
    __syncthreads();
    if (wid > 0) s += warp_sums[wid - 1];
    if (i <= N_NODES) g_off[i] = s;
    if (threadIdx.x == SCAN_B - 1) g_part[blockIdx.x] = s;
}

// Exclusive scan of the (<=128) block partials with one 128-thread block.
__global__ __launch_bounds__(128) void k_scan2(int nb) {
    __shared__ int ws4[4];
    int i = threadIdx.x;
    int lane = i & 31, wid = i >> 5;
    int v = (i < nb) ? g_part[i] : 0;
    int s = v;
#pragma unroll
    for (int d = 1; d < 32; d <<= 1) {
        int t = __shfl_up_sync(~0u, s, d);
        if (lane >= d) s += t;
    }
    if (lane == 31) ws4[wid] = s;
    __syncthreads();
    if (wid == 0 && lane < 4) {
        int w = ws4[lane];
#pragma unroll
        for (int d = 1; d < 4; d <<= 1) {
            int t = __shfl_up_sync(0xFu, w, d);
            if (lane >= d) w += t;
        }
        ws4[lane] = w;
    }
    __syncthreads();
    if (wid > 0) s += ws4[wid - 1];
    if (i < nb) g_part[i] = s - v;   // exclusive
}

// Add block offsets; init scatter cursors to row starts.
__global__ __launch_bounds__(SCAN_B) void k_scan3() {
    int i = blockIdx.x * SCAN_B + threadIdx.x;
    if (i > N_NODES) return;
    int v = g_off[i] + g_part[blockIdx.x];
    g_off[i] = v;
    if (i < N_NODES) g_cur[i] = v;
}

__global__ void k_scatter(const int* __restrict__ dst, int E) {
    int e = blockIdx.x * blockDim.x + threadIdx.x;
    if (e < E) {
        int p = atomicAdd(&g_cur[__ldcs(&dst[e])], 1);
        g_eid[p] = e;
    }
}

// Main pass: 16 threads per node, register accumulation, single store.
__global__ __launch_bounds__(256) void k_econv(
    const float4* __restrict__ x,        // [N, 16]
    const int* __restrict__ src_idx,     // [E]
    const float4* __restrict__ attr,     // [E, 16]
    float4* __restrict__ out)            // [N, 16]
{
    int t = blockIdx.x * blockDim.x + threadIdx.x;
    int n = t >> 4;
    int c = t & 15;
    if (n >= N_NODES) return;

    int k0 = __ldg(&g_off[n]);
    int k1 = __ldg(&g_off[n + 1]);

    float4 acc = make_float4(0.f, 0.f, 0.f, 0.f);

    if (k0 < k1) {
        int e  = __ldg(&g_eid[k0]);
        int sr = __ldg(&src_idx[e]);
        for (int k = k0; k < k1; k++) {
            // prefetch next edge's indices to break the dependent chain
            int e_n = 0, sr_n = 0;
            if (k + 1 < k1) {
                e_n  = __ldg(&g_eid[k + 1]);
                sr_n = __ldg(&src_idx[e_n]);
            }
            float4 av = __ldcs(&attr[(size_t)e * D4 + c]);
            float4 xv = __ldg(&x[(size_t)sr * D4 + c]);
            acc.x += av.x * xv.x;
            acc.y += av.y * xv.y;
            acc.z += av.z * xv.z;
            acc.w += av.w * xv.w;
            e = e_n; sr = sr_n;
        }
    }
    out[(size_t)n * D4 + c] = acc;   // also writes zeros for degree-0 nodes
}

extern "C" void kernel_launch(void* const* d_in, const int* in_sizes, int n_in,
                              void* d_out, int out_size) {
    const float4* x = (const float4*)d_in[0];
    const int* edge_index = (const int*)d_in[1];
    const float4* edge_attr = (const float4*)d_in[2];

    int E = in_sizes[1] / 2;                 // 1,000,000
    const int* dst_idx = edge_index;         // row 0
    const int* src_idx = edge_index + E;     // row 1

    int nb_off = (N_NODES + 1 + 255) / 256;
    int nb_e   = (E + 255) / 256;

    k_zero_off<<<nb_off, 256>>>();
    k_hist<<<nb_e, 256>>>(dst_idx, E);
    k_scan1<<<SCAN_NB, SCAN_B>>>();
    k_scan2<<<1, 128>>>(SCAN_NB);
    k_scan3<<<SCAN_NB, SCAN_B>>>();
    k_scatter<<<nb_e, 256>>>(dst_idx, E);

    int total = N_NODES * D4;                // 1.6M threads
    k_econv<<<(total + 255) / 256, 256>>>(x, src_idx, edge_attr, (float4*)d_out);
}